// round 8
// baseline (speedup 1.0000x reference)
#include <cuda_runtime.h>
#include <cstdint>

#define DEV_INLINE __device__ __forceinline__
typedef unsigned long long ull;

// ---------------- scratch (device globals; no allocations allowed) ----------
__device__ float g_c1[16 * 1024 * 256];            // after conv1 + frame grouping
__device__ float g_c2[16 * 1024 * 256];            // after conv2
__device__ float g_c3[16 * 4096 * 256];            // after tconv
__device__ float g_gx[(size_t)16 * 8 * 4096 * 96]; // gates_x, GRU-CTA-sliced layout
__device__ float g_w2t[512 * 256];                 // W2 transposed: [kk][o]
__device__ float g_wihT[256 * 768];                // W_ih transposed: [c][g]

// ---------------- packed f32x2 helpers --------------------------------------
DEV_INLINE ull dup2(float x) {
    ull r; asm("mov.b64 %0, {%1, %1};" : "=l"(r) : "f"(x)); return r;
}
DEV_INLINE void fma2(ull& d, ull a, ull b) {
    asm("fma.rn.f32x2 %0, %1, %2, %0;" : "+l"(d) : "l"(a), "l"(b));
}
DEV_INLINE void unpack2(ull v, float& x, float& y) {
    asm("mov.b64 {%0, %1}, %2;" : "=f"(x), "=f"(y) : "l"(v));
}
DEV_INLINE ull pack2(float x, float y) {
    ull r; asm("mov.b64 %0, {%1, %2};" : "=l"(r) : "f"(x), "f"(y)); return r;
}

// ---------------- fast activations (MUFU ex2 + rcp; rel err ~1e-6) ----------
DEV_INLINE float fast_tanh(float x) {
    x = fminf(15.f, fmaxf(-15.f, x));
    float e = __expf(2.f * x);
    return __fdividef(e - 1.f, e + 1.f);
}
DEV_INLINE float fast_sig(float x) {
    x = fminf(30.f, fmaxf(-30.f, x));
    return __fdividef(1.f, 1.f + __expf(-x));
}

// ---------------- cluster / mbarrier helpers (LSU path, fence-free) ---------
DEV_INLINE uint32_t smem_u32(const void* p) {
    return (uint32_t)__cvta_generic_to_shared(p);
}
DEV_INLINE uint32_t mapa_u32(uint32_t laddr, int rank) {
    uint32_t r;
    asm volatile("mapa.shared::cluster.u32 %0, %1, %2;" : "=r"(r) : "r"(laddr), "r"(rank));
    return r;
}
DEV_INLINE void mbar_init(uint32_t a, uint32_t cnt) {
    asm volatile("mbarrier.init.shared.b64 [%0], %1;" :: "r"(a), "r"(cnt) : "memory");
}
// acquire at CLUSTER scope: pairs with remote arrives' release
DEV_INLINE void mbar_wait_acq_cluster(uint32_t a, uint32_t phase) {
    asm volatile(
        "{\n\t"
        ".reg .pred P;\n\t"
        "WL%=:\n\t"
        "mbarrier.try_wait.parity.acquire.cluster.shared::cta.b64 P, [%0], %1, 0x989680;\n\t"
        "@P bra WD%=;\n\t"
        "bra WL%=;\n\t"
        "WD%=:\n\t"
        "}" :: "r"(a), "r"(phase) : "memory");
}
// plain LSU remote smem store (synchronous DSMEM path, ~215 cyc flight)
DEV_INLINE void st_cluster_b64(uint32_t raddr, ull v) {
    asm volatile("st.shared::cluster.b64 [%0], %1;" :: "r"(raddr), "l"(v) : "memory");
}
// remote mbarrier arrive with RELEASE at cluster scope: orders THIS thread's
// prior cluster stores before the arrive (no fence needed).
DEV_INLINE void arrive_release_cluster(uint32_t raddr) {
    asm volatile("mbarrier.arrive.release.cluster.shared::cluster.b64 _, [%0];"
                 :: "r"(raddr) : "memory");
}
DEV_INLINE void cluster_sync_() {
    asm volatile("barrier.cluster.arrive.aligned;" ::: "memory");
    asm volatile("barrier.cluster.wait.aligned;" ::: "memory");
}

// ============================================================================
// Kernel A: conv1 (k=1 pointwise, 47->64) + tanh + frame grouping (B,1024,256)
// ============================================================================
__global__ __launch_bounds__(256) void conv1_kernel(
    const float* __restrict__ feat, const float* __restrict__ W1,
    const float* __restrict__ b1)
{
    __shared__ float sW[64 * 47];
    __shared__ float sb[64];
    __shared__ float sx[32 * 47];
    const int tid = threadIdx.x;
    const int b = blockIdx.y;
    const int f0 = blockIdx.x * 32;
    for (int i = tid; i < 64 * 47; i += 256) sW[i] = W1[i];
    if (tid < 64) sb[tid] = b1[tid];
    const float* fp = feat + ((size_t)b * 4096 + f0) * 47;
    for (int i = tid; i < 32 * 47; i += 256) sx[i] = fp[i];
    __syncthreads();
#pragma unroll
    for (int r = 0; r < 8; r++) {
        int idx = tid + 256 * r;
        int f = idx >> 6, h = idx & 63;
        float acc = sb[h];
#pragma unroll
        for (int i = 0; i < 47; i++) acc = fmaf(sx[f * 47 + i], sW[h * 47 + i], acc);
        int gf = f0 + f;
        g_c1[((size_t)b * 1024 + (gf >> 2)) * 256 + ((gf & 3) << 6) + h] = fast_tanh(acc);
    }
}

// ============================================================================
// Prep: both weight transposes in ONE kernel.
// ============================================================================
__global__ __launch_bounds__(768) void prep_kernel(
    const float* __restrict__ W2, const float* __restrict__ W_ih)
{
    int blk = blockIdx.x;
    int t = threadIdx.x;
    if (blk < 512) {
        if (t < 256)
            g_w2t[blk * 256 + t] = W2[t * 512 + ((blk & 255) << 1) + (blk >> 8)];
    } else {
        int c = blk - 512;                 // 0..255
        g_wihT[c * 768 + t] = W_ih[t * 256 + c];
    }
}

// ============================================================================
// Shared GEMM skeleton (128x128 tile, BK=16, 256 thr, 8x8 micro, f32x2 FMA)
// ============================================================================
template <int MODE>
__global__ __launch_bounds__(256) void gemm_kernel(
    const float* __restrict__ Bext, const float* __restrict__ bias)
{
    __shared__ float As[16][136];
    __shared__ float Bs[16][128];
    const int tid = threadIdx.x;
    const int tx = tid & 15, ty = tid >> 4;
    const int m0 = blockIdx.x * 128;
    const int n0 = blockIdx.y * 128;
    constexpr int K   = (MODE == 0) ? 512 : 256;
    constexpr int Nld = (MODE == 0) ? 256 : (MODE == 1 ? 1024 : 768);
    const float* Bm = (MODE == 0) ? g_w2t : (MODE == 1 ? Bext : g_wihT);
    const float* Amat = (MODE == 1) ? g_c2 : g_c3;

    ull acc[8][4];
#pragma unroll
    for (int i = 0; i < 8; i++)
#pragma unroll
        for (int j = 0; j < 4; j++) acc[i][j] = 0ULL;

    for (int k0 = 0; k0 < K; k0 += 16) {
#pragma unroll
        for (int it = 0; it < 2; it++) {
            int idx = tid + it * 256;
            int row = idx >> 2;
            int kq = (idx & 3) << 2;
            int m = m0 + row;
            float4 v;
            if (MODE == 0) {
                if (k0 < 256) {
                    if ((m & 1023) != 0)
                        v = *(const float4*)&g_c1[((size_t)m - 1) * 256 + k0 + kq];
                    else
                        v = make_float4(0.f, 0.f, 0.f, 0.f);
                } else {
                    v = *(const float4*)&g_c1[(size_t)m * 256 + (k0 - 256) + kq];
                }
            } else {
                v = *(const float4*)&Amat[(size_t)m * 256 + k0 + kq];
            }
            As[kq + 0][row] = v.x; As[kq + 1][row] = v.y;
            As[kq + 2][row] = v.z; As[kq + 3][row] = v.w;
        }
#pragma unroll
        for (int it = 0; it < 2; it++) {
            int idx = tid + it * 256;
            int kr = idx >> 5;
            int nq = (idx & 31) << 2;
            *(float4*)&Bs[kr][nq] = *(const float4*)&Bm[(size_t)(k0 + kr) * Nld + n0 + nq];
        }
        __syncthreads();
#pragma unroll
        for (int kk = 0; kk < 16; kk++) {
            float4 a0 = *(const float4*)&As[kk][ty * 8];
            float4 a1 = *(const float4*)&As[kk][ty * 8 + 4];
            ulonglong2 bb0 = *(const ulonglong2*)&Bs[kk][tx * 8];
            ulonglong2 bb1 = *(const ulonglong2*)&Bs[kk][tx * 8 + 4];
            ull ad[8] = {dup2(a0.x), dup2(a0.y), dup2(a0.z), dup2(a0.w),
                         dup2(a1.x), dup2(a1.y), dup2(a1.z), dup2(a1.w)};
            ull bp[4] = {bb0.x, bb0.y, bb1.x, bb1.y};
#pragma unroll
            for (int mm = 0; mm < 8; mm++)
#pragma unroll
                for (int np = 0; np < 4; np++) fma2(acc[mm][np], ad[mm], bp[np]);
        }
        __syncthreads();
    }
#pragma unroll
    for (int mm = 0; mm < 8; mm++) {
        int m = m0 + ty * 8 + mm;
#pragma unroll
        for (int np = 0; np < 4; np++) {
            float f0, f1;
            unpack2(acc[mm][np], f0, f1);
#pragma unroll
            for (int e = 0; e < 2; e++) {
                float f = e ? f1 : f0;
                int n = n0 + tx * 8 + np * 2 + e;
                if (MODE == 0) {
                    g_c2[(size_t)m * 256 + n] = fast_tanh(f + __ldg(&bias[n]));
                } else if (MODE == 1) {
                    int o = n >> 2, kcv = n & 3;
                    float v = fast_tanh(f + __ldg(&bias[o]));
                    int bb = m >> 10, t = m & 1023;
                    g_c3[((size_t)bb * 4096 + 4 * t + kcv) * 256 + o] = v;
                } else {
                    float v = f + __ldg(&bias[n]);
                    int bb = m >> 12, t = m & 4095;
                    int gate = n >> 8, ch = n & 255;
                    int sl = ch >> 5, loc = (gate << 5) + (ch & 31);
                    g_gx[((size_t)(bb * 8 + sl) * 4096 + t) * 96 + loc] = v;
                }
            }
        }
    }
}

// ============================================================================
// GRU: 16 clusters x 8 CTAs. CTA (b, s) owns channels [32s, 32s+32).
// FENCE-FREE LSU exchange: each even lane stores its b64 pair to all 8
// peers (plain st.shared::cluster) then arrives on all 8 peers' mbarriers
// with mbarrier.arrive.RELEASE.CLUSTER (self-ordering: release covers the
// arriving thread's own prior stores). Barrier count = 8 CTAs x 16 lanes
// = 128. Consumer: lane-0 try_wait.acquire.cluster; no fences anywhere.
// ============================================================================
__global__ void __cluster_dims__(8, 1, 1) __launch_bounds__(384, 1)
gru_kernel(const float* __restrict__ W_hh, const float* __restrict__ b_hh,
           float* __restrict__ out)
{
    __shared__ __align__(16) float h_buf[2][256];
    __shared__ float gates_s[96];
    __shared__ __align__(8) ull mbar[2];
    const int tid = threadIdx.x;
    const int s = blockIdx.x & 7;
    const int b = blockIdx.x >> 3;
    const int p = tid >> 2, kc = tid & 3;   // 96 rows x 4 K-chunks of 64
    const int grow = ((p >> 5) << 8) + (s << 5) + (p & 31);  // global gate row

    // 64 weights per thread as 32 f32x2 regs
    ull wp[32];
    const ull* Wp = (const ull*)W_hh;
#pragma unroll
    for (int j = 0; j < 32; j++) wp[j] = Wp[grow * 128 + kc * 32 + j];
    if (tid < 256) h_buf[0][tid] = 0.f;

    const uint32_t mb0 = smem_u32(&mbar[0]);
    const uint32_t mb1 = smem_u32(&mbar[1]);
    if (tid == 0) { mbar_init(mb0, 128); mbar_init(mb1, 128); }

    const size_t gx_base = (size_t)(b * 8 + s) * 4096 * 96;
    float bhr = 0.f, bhz = 0.f, bhn = 0.f, gxr = 0.f, gxz = 0.f, gxn = 0.f;
    float hold = 0.f;
    uint32_t rh[2][8], rm[2][8];  // even lanes: remote h slots + barriers
    if (tid < 32) {
        int ch = (s << 5) + tid;
        bhr = b_hh[ch]; bhz = b_hh[256 + ch]; bhn = b_hh[512 + ch];
        gxr = g_gx[gx_base + tid];
        gxz = g_gx[gx_base + 32 + tid];
        gxn = g_gx[gx_base + 64 + tid];
        if ((tid & 1) == 0) {
            uint32_t l0 = smem_u32(&h_buf[0][(s << 5) + tid]);
            uint32_t l1 = smem_u32(&h_buf[1][(s << 5) + tid]);
#pragma unroll
            for (int pr = 0; pr < 8; pr++) {
                rh[0][pr] = mapa_u32(l0, pr);
                rh[1][pr] = mapa_u32(l1, pr);
                rm[0][pr] = mapa_u32(mb0, pr);
                rm[1][pr] = mapa_u32(mb1, pr);
            }
        }
    }
    __syncthreads();
    cluster_sync_();  // all mbarriers initialized before any remote op

    int ph0 = 0, ph1 = 0;
    for (int t = 0; t < 4096; t++) {
        const int bin = (t + 1) & 1;      // incoming buffer for h_{t+1}
        const bool last = (t == 4095);

        // ---- f32x2 gemv: row grow, h chunk [64kc, 64kc+64) ----
        ull accA = 0ULL, accB = 0ULL;
        const ulonglong2* hb = (const ulonglong2*)&h_buf[t & 1][kc * 64];
#pragma unroll
        for (int j = 0; j < 16; j++) {
            ulonglong2 hv = hb[j];
            fma2(accA, wp[2 * j + 0], hv.x);
            fma2(accB, wp[2 * j + 1], hv.y);
        }
        float ax, ay, bx, by;
        unpack2(accA, ax, ay); unpack2(accB, bx, by);
        float r0 = (ax + ay) + (bx + by);
        r0 += __shfl_xor_sync(0xffffffffu, r0, 1);
        r0 += __shfl_xor_sync(0xffffffffu, r0, 2);
        if (kc == 0) gates_s[p] = r0;
        __syncthreads();

        if (tid < 32) {
            float dr = gates_s[tid] + bhr;
            float dz = gates_s[32 + tid] + bhz;
            float dn = gates_s[64 + tid] + bhn;
            float r = fast_sig(gxr + dr);
            float z = fast_sig(gxz + dz);
            float n = fast_tanh(gxn + r * dn);
            float hnew = fmaf(z, hold - n, n);  // (1-z)n + z*h
            hold = hnew;
            // pack adjacent-lane pairs; even lanes store + arrive per peer
            float hpart = __shfl_down_sync(0xffffffffu, hnew, 1);
            if (((tid & 1) == 0) && !last) {
                ull v2 = pack2(hnew, hpart);
#pragma unroll
                for (int pr = 0; pr < 8; pr++)
                    st_cluster_b64(rh[bin][pr], v2);
#pragma unroll
                for (int pr = 0; pr < 8; pr++)
                    arrive_release_cluster(rm[bin][pr]);
            }
            out[((size_t)b * 4096 + t) * 256 + (s << 5) + tid] = hnew;
            // prefetch next step's x-gates (off critical path)
            int tn = last ? t : (t + 1);
            size_t off = gx_base + (size_t)tn * 96;
            gxr = __ldg(&g_gx[off + tid]);
            gxz = __ldg(&g_gx[off + 32 + tid]);
            gxn = __ldg(&g_gx[off + 64 + tid]);
        }
        // ---- single-lane wait; everyone else parks at the barrier ----
        if (tid == 0 && !last) {
            if (bin) { mbar_wait_acq_cluster(mb1, ph1); ph1 ^= 1; }
            else     { mbar_wait_acq_cluster(mb0, ph0); ph0 ^= 1; }
        }
        __syncthreads();
    }
    cluster_sync_();  // no CTA exits while peers may still target its smem
}

// ============================================================================
extern "C" void kernel_launch(void* const* d_in, const int* in_sizes, int n_in,
                              void* d_out, int out_size)
{
    const float* features = (const float*)d_in[0];
    const float* W1   = (const float*)d_in[1];
    const float* b1   = (const float*)d_in[2];
    const float* W2   = (const float*)d_in[3];
    const float* b2   = (const float*)d_in[4];
    const float* Wt   = (const float*)d_in[5];
    const float* bt   = (const float*)d_in[6];
    const float* W_ih = (const float*)d_in[7];
    const float* W_hh = (const float*)d_in[8];
    const float* b_ih = (const float*)d_in[9];
    const float* b_hh = (const float*)d_in[10];
    float* out = (float*)d_out;

    conv1_kernel<<<dim3(128, 16), 256>>>(features, W1, b1);
    prep_kernel<<<768, 768>>>(W2, W_ih);
    gemm_kernel<0><<<dim3(128, 2), 256>>>(nullptr, b2);
    gemm_kernel<1><<<dim3(128, 8), 256>>>(Wt, bt);
    gemm_kernel<2><<<dim3(512, 6), 256>>>(nullptr, b_ih);
    gru_kernel<<<128, 384>>>(W_hh, b_hh, out);
}

// round 9
// speedup vs baseline: 1.2377x; 1.2377x over previous
#include <cuda_runtime.h>
#include <cstdint>

#define DEV_INLINE __device__ __forceinline__
typedef unsigned long long ull;

// ---------------- scratch (device globals; no allocations allowed) ----------
__device__ float g_c1[16 * 1024 * 256];            // after conv1 + frame grouping
__device__ float g_c2[16 * 1024 * 256];            // after conv2
__device__ float g_c3[16 * 4096 * 256];            // after tconv
__device__ float g_gx[(size_t)16 * 8 * 4096 * 96]; // gates_x, GRU-CTA-sliced layout
__device__ float g_w2t[512 * 256];                 // W2 transposed: [kk][o]
__device__ float g_wihT[256 * 768];                // W_ih transposed: [c][g]

// ---------------- packed f32x2 helpers --------------------------------------
DEV_INLINE ull dup2(float x) {
    ull r; asm("mov.b64 %0, {%1, %1};" : "=l"(r) : "f"(x)); return r;
}
DEV_INLINE void fma2(ull& d, ull a, ull b) {
    asm("fma.rn.f32x2 %0, %1, %2, %0;" : "+l"(d) : "l"(a), "l"(b));
}
DEV_INLINE void unpack2(ull v, float& x, float& y) {
    asm("mov.b64 {%0, %1}, %2;" : "=f"(x), "=f"(y) : "l"(v));
}

// ---------------- fast activations (MUFU ex2 + rcp; rel err ~1e-6) ----------
DEV_INLINE float fast_tanh(float x) {
    x = fminf(15.f, fmaxf(-15.f, x));
    float e = __expf(2.f * x);
    return __fdividef(e - 1.f, e + 1.f);
}
DEV_INLINE float fast_sig(float x) {
    x = fminf(30.f, fmaxf(-30.f, x));
    return __fdividef(1.f, 1.f + __expf(-x));
}

// ---------------- cluster / mbarrier helpers (LSU path, fence-free) ---------
DEV_INLINE uint32_t smem_u32(const void* p) {
    return (uint32_t)__cvta_generic_to_shared(p);
}
DEV_INLINE uint32_t mapa_u32(uint32_t laddr, int rank) {
    uint32_t r;
    asm volatile("mapa.shared::cluster.u32 %0, %1, %2;" : "=r"(r) : "r"(laddr), "r"(rank));
    return r;
}
DEV_INLINE void mbar_init(uint32_t a, uint32_t cnt) {
    asm volatile("mbarrier.init.shared.b64 [%0], %1;" :: "r"(a), "r"(cnt) : "memory");
}
// acquire at CLUSTER scope: pairs with remote arrives' release
DEV_INLINE void mbar_wait_acq_cluster(uint32_t a, uint32_t phase) {
    asm volatile(
        "{\n\t"
        ".reg .pred P;\n\t"
        "WL%=:\n\t"
        "mbarrier.try_wait.parity.acquire.cluster.shared::cta.b64 P, [%0], %1, 0x989680;\n\t"
        "@P bra WD%=;\n\t"
        "bra WL%=;\n\t"
        "WD%=:\n\t"
        "}" :: "r"(a), "r"(phase) : "memory");
}
// plain LSU remote smem store (synchronous DSMEM path, ~215 cyc flight)
DEV_INLINE void st_cluster_b64(uint32_t raddr, ull v) {
    asm volatile("st.shared::cluster.b64 [%0], %1;" :: "r"(raddr), "l"(v) : "memory");
}
// remote mbarrier arrive, RELEASE at cluster scope: orders THIS thread's
// prior cluster stores before the arrive (no fence needed).
DEV_INLINE void arrive_release_cluster(uint32_t raddr) {
    asm volatile("mbarrier.arrive.release.cluster.shared::cluster.b64 _, [%0];"
                 :: "r"(raddr) : "memory");
}
DEV_INLINE void cluster_sync_() {
    asm volatile("barrier.cluster.arrive.aligned;" ::: "memory");
    asm volatile("barrier.cluster.wait.aligned;" ::: "memory");
}

// ============================================================================
// Kernel A: conv1 (k=1 pointwise, 47->64) + tanh + frame grouping (B,1024,256)
// ============================================================================
__global__ __launch_bounds__(256) void conv1_kernel(
    const float* __restrict__ feat, const float* __restrict__ W1,
    const float* __restrict__ b1)
{
    __shared__ float sW[64 * 47];
    __shared__ float sb[64];
    __shared__ float sx[32 * 47];
    const int tid = threadIdx.x;
    const int b = blockIdx.y;
    const int f0 = blockIdx.x * 32;
    for (int i = tid; i < 64 * 47; i += 256) sW[i] = W1[i];
    if (tid < 64) sb[tid] = b1[tid];
    const float* fp = feat + ((size_t)b * 4096 + f0) * 47;
    for (int i = tid; i < 32 * 47; i += 256) sx[i] = fp[i];
    __syncthreads();
#pragma unroll
    for (int r = 0; r < 8; r++) {
        int idx = tid + 256 * r;
        int f = idx >> 6, h = idx & 63;
        float acc = sb[h];
#pragma unroll
        for (int i = 0; i < 47; i++) acc = fmaf(sx[f * 47 + i], sW[h * 47 + i], acc);
        int gf = f0 + f;
        g_c1[((size_t)b * 1024 + (gf >> 2)) * 256 + ((gf & 3) << 6) + h] = fast_tanh(acc);
    }
}

// ============================================================================
// Prep: both weight transposes in ONE kernel.
// ============================================================================
__global__ __launch_bounds__(768) void prep_kernel(
    const float* __restrict__ W2, const float* __restrict__ W_ih)
{
    int blk = blockIdx.x;
    int t = threadIdx.x;
    if (blk < 512) {
        if (t < 256)
            g_w2t[blk * 256 + t] = W2[t * 512 + ((blk & 255) << 1) + (blk >> 8)];
    } else {
        int c = blk - 512;                 // 0..255
        g_wihT[c * 768 + t] = W_ih[t * 256 + c];
    }
}

// ============================================================================
// Shared GEMM skeleton (128x128 tile, BK=16, 256 thr, 8x8 micro, f32x2 FMA)
// ============================================================================
template <int MODE>
__global__ __launch_bounds__(256) void gemm_kernel(
    const float* __restrict__ Bext, const float* __restrict__ bias)
{
    __shared__ float As[16][136];
    __shared__ float Bs[16][128];
    const int tid = threadIdx.x;
    const int tx = tid & 15, ty = tid >> 4;
    const int m0 = blockIdx.x * 128;
    const int n0 = blockIdx.y * 128;
    constexpr int K   = (MODE == 0) ? 512 : 256;
    constexpr int Nld = (MODE == 0) ? 256 : (MODE == 1 ? 1024 : 768);
    const float* Bm = (MODE == 0) ? g_w2t : (MODE == 1 ? Bext : g_wihT);
    const float* Amat = (MODE == 1) ? g_c2 : g_c3;

    ull acc[8][4];
#pragma unroll
    for (int i = 0; i < 8; i++)
#pragma unroll
        for (int j = 0; j < 4; j++) acc[i][j] = 0ULL;

    for (int k0 = 0; k0 < K; k0 += 16) {
#pragma unroll
        for (int it = 0; it < 2; it++) {
            int idx = tid + it * 256;
            int row = idx >> 2;
            int kq = (idx & 3) << 2;
            int m = m0 + row;
            float4 v;
            if (MODE == 0) {
                if (k0 < 256) {
                    if ((m & 1023) != 0)
                        v = *(const float4*)&g_c1[((size_t)m - 1) * 256 + k0 + kq];
                    else
                        v = make_float4(0.f, 0.f, 0.f, 0.f);
                } else {
                    v = *(const float4*)&g_c1[(size_t)m * 256 + (k0 - 256) + kq];
                }
            } else {
                v = *(const float4*)&Amat[(size_t)m * 256 + k0 + kq];
            }
            As[kq + 0][row] = v.x; As[kq + 1][row] = v.y;
            As[kq + 2][row] = v.z; As[kq + 3][row] = v.w;
        }
#pragma unroll
        for (int it = 0; it < 2; it++) {
            int idx = tid + it * 256;
            int kr = idx >> 5;
            int nq = (idx & 31) << 2;
            *(float4*)&Bs[kr][nq] = *(const float4*)&Bm[(size_t)(k0 + kr) * Nld + n0 + nq];
        }
        __syncthreads();
#pragma unroll
        for (int kk = 0; kk < 16; kk++) {
            float4 a0 = *(const float4*)&As[kk][ty * 8];
            float4 a1 = *(const float4*)&As[kk][ty * 8 + 4];
            ulonglong2 bb0 = *(const ulonglong2*)&Bs[kk][tx * 8];
            ulonglong2 bb1 = *(const ulonglong2*)&Bs[kk][tx * 8 + 4];
            ull ad[8] = {dup2(a0.x), dup2(a0.y), dup2(a0.z), dup2(a0.w),
                         dup2(a1.x), dup2(a1.y), dup2(a1.z), dup2(a1.w)};
            ull bp[4] = {bb0.x, bb0.y, bb1.x, bb1.y};
#pragma unroll
            for (int mm = 0; mm < 8; mm++)
#pragma unroll
                for (int np = 0; np < 4; np++) fma2(acc[mm][np], ad[mm], bp[np]);
        }
        __syncthreads();
    }
#pragma unroll
    for (int mm = 0; mm < 8; mm++) {
        int m = m0 + ty * 8 + mm;
#pragma unroll
        for (int np = 0; np < 4; np++) {
            float f0, f1;
            unpack2(acc[mm][np], f0, f1);
#pragma unroll
            for (int e = 0; e < 2; e++) {
                float f = e ? f1 : f0;
                int n = n0 + tx * 8 + np * 2 + e;
                if (MODE == 0) {
                    g_c2[(size_t)m * 256 + n] = fast_tanh(f + __ldg(&bias[n]));
                } else if (MODE == 1) {
                    int o = n >> 2, kcv = n & 3;
                    float v = fast_tanh(f + __ldg(&bias[o]));
                    int bb = m >> 10, t = m & 1023;
                    g_c3[((size_t)bb * 4096 + 4 * t + kcv) * 256 + o] = v;
                } else {
                    float v = f + __ldg(&bias[n]);
                    int bb = m >> 12, t = m & 4095;
                    int gate = n >> 8, ch = n & 255;
                    int sl = ch >> 5, loc = (gate << 5) + (ch & 31);
                    g_gx[((size_t)(bb * 8 + sl) * 4096 + t) * 96 + loc] = v;
                }
            }
        }
    }
}

// ============================================================================
// GRU: 16 clusters x 8 CTAs. CTA (b, s) owns channels [32s, 32s+32).
// Exchange with exactly 8 barrier updates per destination per step:
//   warp0 lanes stage h slice in local smem -> __syncwarp -> lane j (j<8)
//   copies 128B to peer j via 16x st.shared::cluster.b64 then ONE
//   mbarrier.arrive.release.cluster (same-thread release orders stores).
// Consumers: per-warp lane-0 try_wait.acquire.cluster + __syncwarp.
// ONE __syncthreads per step (post-gemv, pre-activation).
// ============================================================================
__global__ void __cluster_dims__(8, 1, 1) __launch_bounds__(384, 1)
gru_kernel(const float* __restrict__ W_hh, const float* __restrict__ b_hh,
           float* __restrict__ out)
{
    __shared__ __align__(16) float h_buf[2][256];
    __shared__ __align__(16) float h_stage[2][32];
    __shared__ float gates_s[96];
    __shared__ __align__(8) ull mbar[2];
    const int tid = threadIdx.x;
    const int s = blockIdx.x & 7;
    const int b = blockIdx.x >> 3;
    const int p = tid >> 2, kc = tid & 3;   // 96 rows x 4 K-chunks of 64
    const int grow = ((p >> 5) << 8) + (s << 5) + (p & 31);  // global gate row
    const int warp = tid >> 5, lane = tid & 31;

    // 64 weights per thread as 32 f32x2 regs
    ull wp[32];
    const ull* Wp = (const ull*)W_hh;
#pragma unroll
    for (int j = 0; j < 32; j++) wp[j] = Wp[grow * 128 + kc * 32 + j];
    if (tid < 256) h_buf[0][tid] = 0.f;

    const uint32_t mb0 = smem_u32(&mbar[0]);
    const uint32_t mb1 = smem_u32(&mbar[1]);
    if (tid == 0) { mbar_init(mb0, 8); mbar_init(mb1, 8); }  // 8 arrives/phase

    const size_t gx_base = (size_t)(b * 8 + s) * 4096 * 96;
    float bhr = 0.f, bhz = 0.f, bhn = 0.f, gxr = 0.f, gxz = 0.f, gxn = 0.f;
    float hold = 0.f;
    uint32_t rdst0 = 0, rdst1 = 0, rmb0 = 0, rmb1 = 0;  // warp0 lanes 0-7
    if (warp == 0) {
        int ch = (s << 5) + lane;
        bhr = b_hh[ch]; bhz = b_hh[256 + ch]; bhn = b_hh[512 + ch];
        gxr = g_gx[gx_base + lane];
        gxz = g_gx[gx_base + 32 + lane];
        gxn = g_gx[gx_base + 64 + lane];
        if (lane < 8) {
            rdst0 = mapa_u32(smem_u32(&h_buf[0][s << 5]), lane);
            rdst1 = mapa_u32(smem_u32(&h_buf[1][s << 5]), lane);
            rmb0 = mapa_u32(mb0, lane);
            rmb1 = mapa_u32(mb1, lane);
        }
    }
    __syncthreads();
    cluster_sync_();  // all mbarriers initialized before any remote op

    int ph0 = 0, ph1 = 0;
    for (int t = 0; t < 4096; t++) {
        const int bin = (t + 1) & 1;      // incoming buffer for h_{t+1}
        const bool last = (t == 4095);

        // ---- f32x2 gemv: row grow, h chunk [64kc, 64kc+64) ----
        ull accA = 0ULL, accB = 0ULL;
        const ulonglong2* hb = (const ulonglong2*)&h_buf[t & 1][kc * 64];
#pragma unroll
        for (int j = 0; j < 16; j++) {
            ulonglong2 hv = hb[j];
            fma2(accA, wp[2 * j + 0], hv.x);
            fma2(accB, wp[2 * j + 1], hv.y);
        }
        float ax, ay, bx, by;
        unpack2(accA, ax, ay); unpack2(accB, bx, by);
        float r0 = (ax + ay) + (bx + by);
        r0 += __shfl_xor_sync(0xffffffffu, r0, 1);
        r0 += __shfl_xor_sync(0xffffffffu, r0, 2);
        if (kc == 0) gates_s[p] = r0;
        __syncthreads();   // the ONLY CTA-wide barrier in the step

        if (warp == 0) {
            float dr = gates_s[lane] + bhr;
            float dz = gates_s[32 + lane] + bhz;
            float dn = gates_s[64 + lane] + bhn;
            float r = fast_sig(gxr + dr);
            float z = fast_sig(gxz + dz);
            float n = fast_tanh(gxn + r * dn);
            float hnew = fmaf(z, hold - n, n);  // (1-z)n + z*h
            hold = hnew;
            h_stage[bin][lane] = hnew;          // stage slice locally
            __syncwarp();
            if (lane < 8 && !last) {
                // lane j: copy full 128B slice to peer j, then ONE arrive
                const ulonglong2* sp = (const ulonglong2*)&h_stage[bin][0];
                uint32_t dst = bin ? rdst1 : rdst0;
#pragma unroll
                for (int i = 0; i < 8; i++) {
                    ulonglong2 v = sp[i];
                    st_cluster_b64(dst + i * 16, v.x);
                    st_cluster_b64(dst + i * 16 + 8, v.y);
                }
                arrive_release_cluster(bin ? rmb1 : rmb0);
            }
            out[((size_t)b * 4096 + t) * 256 + (s << 5) + lane] = hnew;
            // prefetch next step's x-gates (off critical path)
            int tn = last ? t : (t + 1);
            size_t off = gx_base + (size_t)tn * 96;
            gxr = __ldg(&g_gx[off + lane]);
            gxz = __ldg(&g_gx[off + 32 + lane]);
            gxn = __ldg(&g_gx[off + 64 + lane]);
        }
        // ---- per-warp wait: lane 0 sleeps on mbarrier, warp parks at syncwarp
        if (!last) {
            if (lane == 0) {
                if (bin) mbar_wait_acq_cluster(mb1, ph1);
                else     mbar_wait_acq_cluster(mb0, ph0);
            }
            __syncwarp();
            if (bin) ph1 ^= 1; else ph0 ^= 1;
        }
    }
    cluster_sync_();  // no CTA exits while peers may still target its smem
}

// ============================================================================
extern "C" void kernel_launch(void* const* d_in, const int* in_sizes, int n_in,
                              void* d_out, int out_size)
{
    const float* features = (const float*)d_in[0];
    const float* W1   = (const float*)d_in[1];
    const float* b1   = (const float*)d_in[2];
    const float* W2   = (const float*)d_in[3];
    const float* b2   = (const float*)d_in[4];
    const float* Wt   = (const float*)d_in[5];
    const float* bt   = (const float*)d_in[6];
    const float* W_ih = (const float*)d_in[7];
    const float* W_hh = (const float*)d_in[8];
    const float* b_ih = (const float*)d_in[9];
    const float* b_hh = (const float*)d_in[10];
    float* out = (float*)d_out;

    conv1_kernel<<<dim3(128, 16), 256>>>(features, W1, b1);
    prep_kernel<<<768, 768>>>(W2, W_ih);
    gemm_kernel<0><<<dim3(128, 2), 256>>>(nullptr, b2);
    gemm_kernel<1><<<dim3(128, 8), 256>>>(Wt, bt);
    gemm_kernel<2><<<dim3(512, 6), 256>>>(nullptr, b_ih);
    gru_kernel<<<128, 384>>>(W_hh, b_hh, out);
}

// round 10
// speedup vs baseline: 2.2204x; 1.7939x over previous
#include <cuda_runtime.h>
#include <cstdint>

#define DEV_INLINE __device__ __forceinline__
typedef unsigned long long ull;

// ---------------- scratch (device globals; no allocations allowed) ----------
__device__ float g_c1[16 * 1024 * 256];            // after conv1 + frame grouping
__device__ float g_c2[16 * 1024 * 256];            // after conv2
__device__ float g_c3[16 * 4096 * 256];            // after tconv
__device__ float g_gx[(size_t)16 * 8 * 4096 * 96]; // gates_x, GRU-CTA-sliced layout
__device__ float g_w2t[512 * 256];                 // W2 transposed: [kk][o]
__device__ float g_wihT[256 * 768];                // W_ih transposed: [c][g]
// GRU h exchange through L2 (no clusters): double-buffered h + epoch flags
__device__ float g_hx[2 * 16 * 256];               // [bin][batch][256]
__device__ int   g_flag[2 * 16 * 32];              // [bin][batch][slot s] (128B padded)

// ---------------- packed f32x2 helpers --------------------------------------
DEV_INLINE ull dup2(float x) {
    ull r; asm("mov.b64 %0, {%1, %1};" : "=l"(r) : "f"(x)); return r;
}
DEV_INLINE void fma2(ull& d, ull a, ull b) {
    asm("fma.rn.f32x2 %0, %1, %2, %0;" : "+l"(d) : "l"(a), "l"(b));
}
DEV_INLINE void unpack2(ull v, float& x, float& y) {
    asm("mov.b64 {%0, %1}, %2;" : "=f"(x), "=f"(y) : "l"(v));
}

// ---------------- fast activations (MUFU ex2 + rcp; rel err ~1e-6) ----------
DEV_INLINE float fast_tanh(float x) {
    x = fminf(15.f, fmaxf(-15.f, x));
    float e = __expf(2.f * x);
    return __fdividef(e - 1.f, e + 1.f);
}
DEV_INLINE float fast_sig(float x) {
    x = fminf(30.f, fmaxf(-30.f, x));
    return __fdividef(1.f, 1.f + __expf(-x));
}

// ---------------- L2 release/acquire exchange helpers ------------------------
DEV_INLINE int ld_acquire_gpu(const int* p) {
    int v;
    asm volatile("ld.acquire.gpu.global.b32 %0, [%1];" : "=r"(v) : "l"(p) : "memory");
    return v;
}
DEV_INLINE void st_release_gpu(int* p, int v) {
    asm volatile("st.release.gpu.global.b32 [%0], %1;" :: "l"(p), "r"(v) : "memory");
}

// ============================================================================
// Kernel A: conv1 (k=1 pointwise, 47->64) + tanh + frame grouping (B,1024,256)
// ============================================================================
__global__ __launch_bounds__(256) void conv1_kernel(
    const float* __restrict__ feat, const float* __restrict__ W1,
    const float* __restrict__ b1)
{
    __shared__ float sW[64 * 47];
    __shared__ float sb[64];
    __shared__ float sx[32 * 47];
    const int tid = threadIdx.x;
    const int b = blockIdx.y;
    const int f0 = blockIdx.x * 32;
    for (int i = tid; i < 64 * 47; i += 256) sW[i] = W1[i];
    if (tid < 64) sb[tid] = b1[tid];
    const float* fp = feat + ((size_t)b * 4096 + f0) * 47;
    for (int i = tid; i < 32 * 47; i += 256) sx[i] = fp[i];
    __syncthreads();
#pragma unroll
    for (int r = 0; r < 8; r++) {
        int idx = tid + 256 * r;
        int f = idx >> 6, h = idx & 63;
        float acc = sb[h];
#pragma unroll
        for (int i = 0; i < 47; i++) acc = fmaf(sx[f * 47 + i], sW[h * 47 + i], acc);
        int gf = f0 + f;
        g_c1[((size_t)b * 1024 + (gf >> 2)) * 256 + ((gf & 3) << 6) + h] = fast_tanh(acc);
    }
}

// ============================================================================
// Prep: both weight transposes in ONE kernel.
// ============================================================================
__global__ __launch_bounds__(768) void prep_kernel(
    const float* __restrict__ W2, const float* __restrict__ W_ih)
{
    int blk = blockIdx.x;
    int t = threadIdx.x;
    if (blk < 512) {
        if (t < 256)
            g_w2t[blk * 256 + t] = W2[t * 512 + ((blk & 255) << 1) + (blk >> 8)];
    } else {
        int c = blk - 512;                 // 0..255
        g_wihT[c * 768 + t] = W_ih[t * 256 + c];
    }
}

// ============================================================================
// Shared GEMM skeleton (128x128 tile, BK=16, 256 thr, 8x8 micro, f32x2 FMA)
// ============================================================================
template <int MODE>
__global__ __launch_bounds__(256) void gemm_kernel(
    const float* __restrict__ Bext, const float* __restrict__ bias)
{
    __shared__ float As[16][136];
    __shared__ float Bs[16][128];
    const int tid = threadIdx.x;
    const int tx = tid & 15, ty = tid >> 4;
    const int m0 = blockIdx.x * 128;
    const int n0 = blockIdx.y * 128;
    constexpr int K   = (MODE == 0) ? 512 : 256;
    constexpr int Nld = (MODE == 0) ? 256 : (MODE == 1 ? 1024 : 768);
    const float* Bm = (MODE == 0) ? g_w2t : (MODE == 1 ? Bext : g_wihT);
    const float* Amat = (MODE == 1) ? g_c2 : g_c3;

    ull acc[8][4];
#pragma unroll
    for (int i = 0; i < 8; i++)
#pragma unroll
        for (int j = 0; j < 4; j++) acc[i][j] = 0ULL;

    for (int k0 = 0; k0 < K; k0 += 16) {
#pragma unroll
        for (int it = 0; it < 2; it++) {
            int idx = tid + it * 256;
            int row = idx >> 2;
            int kq = (idx & 3) << 2;
            int m = m0 + row;
            float4 v;
            if (MODE == 0) {
                if (k0 < 256) {
                    if ((m & 1023) != 0)
                        v = *(const float4*)&g_c1[((size_t)m - 1) * 256 + k0 + kq];
                    else
                        v = make_float4(0.f, 0.f, 0.f, 0.f);
                } else {
                    v = *(const float4*)&g_c1[(size_t)m * 256 + (k0 - 256) + kq];
                }
            } else {
                v = *(const float4*)&Amat[(size_t)m * 256 + k0 + kq];
            }
            As[kq + 0][row] = v.x; As[kq + 1][row] = v.y;
            As[kq + 2][row] = v.z; As[kq + 3][row] = v.w;
        }
#pragma unroll
        for (int it = 0; it < 2; it++) {
            int idx = tid + it * 256;
            int kr = idx >> 5;
            int nq = (idx & 31) << 2;
            *(float4*)&Bs[kr][nq] = *(const float4*)&Bm[(size_t)(k0 + kr) * Nld + n0 + nq];
        }
        __syncthreads();
#pragma unroll
        for (int kk = 0; kk < 16; kk++) {
            float4 a0 = *(const float4*)&As[kk][ty * 8];
            float4 a1 = *(const float4*)&As[kk][ty * 8 + 4];
            ulonglong2 bb0 = *(const ulonglong2*)&Bs[kk][tx * 8];
            ulonglong2 bb1 = *(const ulonglong2*)&Bs[kk][tx * 8 + 4];
            ull ad[8] = {dup2(a0.x), dup2(a0.y), dup2(a0.z), dup2(a0.w),
                         dup2(a1.x), dup2(a1.y), dup2(a1.z), dup2(a1.w)};
            ull bp[4] = {bb0.x, bb0.y, bb1.x, bb1.y};
#pragma unroll
            for (int mm = 0; mm < 8; mm++)
#pragma unroll
                for (int np = 0; np < 4; np++) fma2(acc[mm][np], ad[mm], bp[np]);
        }
        __syncthreads();
    }
#pragma unroll
    for (int mm = 0; mm < 8; mm++) {
        int m = m0 + ty * 8 + mm;
#pragma unroll
        for (int np = 0; np < 4; np++) {
            float f0, f1;
            unpack2(acc[mm][np], f0, f1);
#pragma unroll
            for (int e = 0; e < 2; e++) {
                float f = e ? f1 : f0;
                int n = n0 + tx * 8 + np * 2 + e;
                if (MODE == 0) {
                    g_c2[(size_t)m * 256 + n] = fast_tanh(f + __ldg(&bias[n]));
                } else if (MODE == 1) {
                    int o = n >> 2, kcv = n & 3;
                    float v = fast_tanh(f + __ldg(&bias[o]));
                    int bb = m >> 10, t = m & 1023;
                    g_c3[((size_t)bb * 4096 + 4 * t + kcv) * 256 + o] = v;
                } else {
                    float v = f + __ldg(&bias[n]);
                    int bb = m >> 12, t = m & 4095;
                    int gate = n >> 8, ch = n & 255;
                    int sl = ch >> 5, loc = (gate << 5) + (ch & 31);
                    g_gx[((size_t)(bb * 8 + sl) * 4096 + t) * 96 + loc] = v;
                }
            }
        }
    }
}

// ============================================================================
// GRU: 128 independent CTAs (16 batches x 8 slots). NO clusters.
// CTA (b, s) owns channels [32s, 32s+32). h exchanged through L2:
//   warp0: activation -> STG 128B h slice -> syncwarp -> lane0 release-flag
//   warp1: lanes 0-7 acquire-poll 8 flags (==t+1) -> syncwarp -> __ldcv copy
//          of full 256-float h into smem h_buf[bin]
// Exact-equality flag compare is replay-safe (slot last held t-1's value).
// ============================================================================
__global__ void __launch_bounds__(384, 1)
gru_kernel(const float* __restrict__ W_hh, const float* __restrict__ b_hh,
           float* __restrict__ out)
{
    __shared__ __align__(16) float h_buf[2][256];
    __shared__ float gates_s[96];
    const int tid = threadIdx.x;
    const int s = blockIdx.x & 7;
    const int b = blockIdx.x >> 3;
    const int p = tid >> 2, kc = tid & 3;   // 96 rows x 4 K-chunks of 64
    const int grow = ((p >> 5) << 8) + (s << 5) + (p & 31);  // global gate row
    const int warp = tid >> 5, lane = tid & 31;

    // 64 weights per thread as 32 f32x2 regs
    ull wp[32];
    const ull* Wp = (const ull*)W_hh;
#pragma unroll
    for (int j = 0; j < 32; j++) wp[j] = Wp[grow * 128 + kc * 32 + j];
    if (tid < 256) h_buf[0][tid] = 0.f;

    const size_t gx_base = (size_t)(b * 8 + s) * 4096 * 96;
    float bhr = 0.f, bhz = 0.f, bhn = 0.f, gxr = 0.f, gxz = 0.f, gxn = 0.f;
    float hold = 0.f;
    if (warp == 0) {
        int ch = (s << 5) + lane;
        bhr = b_hh[ch]; bhz = b_hh[256 + ch]; bhn = b_hh[512 + ch];
        gxr = g_gx[gx_base + lane];
        gxz = g_gx[gx_base + 32 + lane];
        gxn = g_gx[gx_base + 64 + lane];
    }
    __syncthreads();

    for (int t = 0; t < 4096; t++) {
        const int par = t & 1;
        const int bin = par ^ 1;          // buffer/flag set for h_{t+1}
        const bool last = (t == 4095);

        // ---- f32x2 gemv: row grow, h chunk [64kc, 64kc+64) ----
        ull accA = 0ULL, accB = 0ULL;
        const ulonglong2* hb = (const ulonglong2*)&h_buf[par][kc * 64];
#pragma unroll
        for (int j = 0; j < 16; j++) {
            ulonglong2 hv = hb[j];
            fma2(accA, wp[2 * j + 0], hv.x);
            fma2(accB, wp[2 * j + 1], hv.y);
        }
        float ax, ay, bx, by;
        unpack2(accA, ax, ay); unpack2(accB, bx, by);
        float r0 = (ax + ay) + (bx + by);
        r0 += __shfl_xor_sync(0xffffffffu, r0, 1);
        r0 += __shfl_xor_sync(0xffffffffu, r0, 2);
        if (kc == 0) gates_s[p] = r0;
        __syncthreads();

        if (warp == 0) {
            // ---- activation for this CTA's 32 channels ----
            float dr = gates_s[lane] + bhr;
            float dz = gates_s[32 + lane] + bhz;
            float dn = gates_s[64 + lane] + bhn;
            float r = fast_sig(gxr + dr);
            float z = fast_sig(gxz + dz);
            float n = fast_tanh(gxn + r * dn);
            float hnew = fmaf(z, hold - n, n);  // (1-z)n + z*h
            hold = hnew;
            if (!last) {
                // publish slice: one 128B line + release-flag
                g_hx[(bin * 16 + b) * 256 + (s << 5) + lane] = hnew;
                __syncwarp();
                if (lane == 0)
                    st_release_gpu(&g_flag[(bin * 16 + b) * 32 + s], t + 1);
            }
            out[((size_t)b * 4096 + t) * 256 + (s << 5) + lane] = hnew;
            // prefetch next step's x-gates (off critical path)
            int tn = last ? t : (t + 1);
            size_t off = gx_base + (size_t)tn * 96;
            gxr = __ldg(&g_gx[off + lane]);
            gxz = __ldg(&g_gx[off + 32 + lane]);
            gxn = __ldg(&g_gx[off + 64 + lane]);
        } else if (warp == 1 && !last) {
            // ---- gather h_{t+1}: poll 8 flags, then copy 256 floats ----
            if (lane < 8) {
                const int* fp = &g_flag[(bin * 16 + b) * 32 + lane];
                while (ld_acquire_gpu(fp) != t + 1) { }
            }
            __syncwarp();
            const float4* src = (const float4*)&g_hx[(bin * 16 + b) * 256];
            float4 v0 = __ldcv(src + lane);
            float4 v1 = __ldcv(src + 32 + lane);
            ((float4*)&h_buf[bin][0])[lane] = v0;
            ((float4*)&h_buf[bin][0])[32 + lane] = v1;
        }
        __syncthreads();
    }
}

// ============================================================================
extern "C" void kernel_launch(void* const* d_in, const int* in_sizes, int n_in,
                              void* d_out, int out_size)
{
    const float* features = (const float*)d_in[0];
    const float* W1   = (const float*)d_in[1];
    const float* b1   = (const float*)d_in[2];
    const float* W2   = (const float*)d_in[3];
    const float* b2   = (const float*)d_in[4];
    const float* Wt   = (const float*)d_in[5];
    const float* bt   = (const float*)d_in[6];
    const float* W_ih = (const float*)d_in[7];
    const float* W_hh = (const float*)d_in[8];
    const float* b_ih = (const float*)d_in[9];
    const float* b_hh = (const float*)d_in[10];
    float* out = (float*)d_out;

    conv1_kernel<<<dim3(128, 16), 256>>>(features, W1, b1);
    prep_kernel<<<768, 768>>>(W2, W_ih);
    gemm_kernel<0><<<dim3(128, 2), 256>>>(nullptr, b2);
    gemm_kernel<1><<<dim3(128, 8), 256>>>(Wt, bt);
    gemm_kernel<2><<<dim3(512, 6), 256>>>(nullptr, b_ih);
    gru_kernel<<<128, 384>>>(W_hh, b_hh, out);
}